// round 12
// baseline (speedup 1.0000x reference)
#include <cuda_runtime.h>
#include <cuda_bf16.h>

// FrozenBNBStableEmbedding: blockwise-int8 dequant embedding gather + LayerNorm.
//
// Inputs (metadata order):
//   0: x         int32  [8, 2048]    token ids (16384)
//   1: weight_i8 int32  [50304,1024] code indices 0..255
//   2: absmax    f32    [12576]      per-4096-elem block scale == per (row>>2)
//   3: code      f32    [256]        dequant codebook
//   4: ln_weight f32    [1024]
//   5: ln_bias   f32    [1024]
// Output: f32 [8, 2048, 1024]
//
// WARP-PER-TOKEN, grid-stride pipeline:
//   - 8 int4 gathers/lane per token (MLP=8), prefetched one token ahead
//   - codes PRMT-packed to 8 regs; values re-looked-up at store time
//     (drops v[32]+c[8] register pressure -> 4 CTAs/SM instead of 2)
//   - codebook replicated 32x in shared: bank == lane, conflict-free
//   - zero block barriers in the main loop (warp shfl reductions only)

#define D 1024
#define V 50304
#define EPS 1e-5f
#define WARPS_PER_CTA 8

__global__ __launch_bounds__(256, 4)
void frozen_bnb_emb_ln_kernel(const int* __restrict__ x,
                              const int* __restrict__ weight_i8,
                              const float* __restrict__ absmax,
                              const float* __restrict__ code,
                              const float* __restrict__ ln_weight,
                              const float* __restrict__ ln_bias,
                              float* __restrict__ out,
                              int n_tokens)
{
    __shared__ float  s_rep[256 * 32];   // s_rep[idx*32 + lane] == code[idx]
    __shared__ float4 s_w[256];          // ln_weight as float4
    __shared__ float4 s_b[256];          // ln_bias  as float4

    const int tid  = threadIdx.x;
    const int warp = tid >> 5;
    const int lane = tid & 31;

    // ---- One-time staging (only barrier in the kernel) ----
    {
        const float cv = __ldg(&code[tid]);
        float* row = &s_rep[tid * 32];
        #pragma unroll
        for (int k = 0; k < 32; k++)
            row[(lane + k) & 31] = cv;           // distinct bank per lane
        s_w[tid] = __ldg(reinterpret_cast<const float4*>(ln_weight) + tid);
        s_b[tid] = __ldg(reinterpret_cast<const float4*>(ln_bias) + tid);
    }
    __syncthreads();

    const int stride = gridDim.x * WARPS_PER_CTA;        // total warps
    int tok = blockIdx.x * WARPS_PER_CTA + warp;
    if (tok >= n_tokens) return;

    // ---- Cold prefetch of first token ----
    int4  raw[8];
    float scale;
    {
        int r = min(max(__ldg(&x[tok]), 0), V - 1);
        scale = __ldg(&absmax[r >> 2]);
        const int4* wr = reinterpret_cast<const int4*>(weight_i8 + (long long)r * D);
        #pragma unroll
        for (int j = 0; j < 8; j++)
            raw[j] = __ldg(wr + j * 32 + lane);
    }

    while (true) {
        // ---- 1) Pack codes: 4 bytes -> 1 reg (frees raw[] for the prefetch) ----
        unsigned pk[8];
        #pragma unroll
        for (int j = 0; j < 8; j++) {
            unsigned lo = __byte_perm((unsigned)raw[j].x, (unsigned)raw[j].y, 0x0040);
            unsigned hi = __byte_perm((unsigned)raw[j].z, (unsigned)raw[j].w, 0x0040);
            pk[j] = __byte_perm(lo, hi, 0x5410);   // [x0 y0 z0 w0]
        }

        // ---- 2) Issue next token's gather NOW (overlaps everything below) ----
        const int ntok = tok + stride;
        const bool have_next = (ntok < n_tokens);
        float nscale = 0.0f;
        if (have_next) {
            int rn = min(max(__ldg(&x[ntok]), 0), V - 1);
            nscale = __ldg(&absmax[rn >> 2]);
            const int4* wr = reinterpret_cast<const int4*>(weight_i8 + (long long)rn * D);
            #pragma unroll
            for (int j = 0; j < 8; j++)
                raw[j] = __ldg(wr + j * 32 + lane);
        }

        // ---- 3) Pass 1: dequant lookups, accumulate stats ----
        float s = 0.0f, sq = 0.0f;
        #pragma unroll
        for (int j = 0; j < 8; j++) {
            float a0 = s_rep[((pk[j]      ) & 255u) * 32 + lane];
            float a1 = s_rep[((pk[j] >>  8) & 255u) * 32 + lane];
            float a2 = s_rep[((pk[j] >> 16) & 255u) * 32 + lane];
            float a3 = s_rep[( pk[j] >> 24        ) * 32 + lane];
            s  += a0 + a1 + a2 + a3;
            sq += a0*a0 + a1*a1 + a2*a2 + a3*a3;
        }
        s  *= scale;
        sq *= scale * scale;

        // ---- 4) Warp-only LayerNorm stats ----
        #pragma unroll
        for (int off = 16; off > 0; off >>= 1) {
            s  += __shfl_xor_sync(0xFFFFFFFFu, s,  off);
            sq += __shfl_xor_sync(0xFFFFFFFFu, sq, off);
        }
        const float mean = s * (1.0f / D);
        const float var  = sq * (1.0f / D) - mean * mean;
        const float rstd = rsqrtf(var + EPS);
        const float a_mul = scale * rstd;          // v*rstd = code*scale*rstd
        const float a_sub = mean * rstd;           // (v-mean)*rstd = code*a_mul - a_sub

        // ---- 5) Pass 2: re-lookup, affine, coalesced float4 stores ----
        float4* orow = reinterpret_cast<float4*>(out + (long long)tok * D);
        #pragma unroll
        for (int j = 0; j < 8; j++) {
            float a0 = s_rep[((pk[j]      ) & 255u) * 32 + lane];
            float a1 = s_rep[((pk[j] >>  8) & 255u) * 32 + lane];
            float a2 = s_rep[((pk[j] >> 16) & 255u) * 32 + lane];
            float a3 = s_rep[( pk[j] >> 24        ) * 32 + lane];
            const float4 w4 = s_w[j * 32 + lane];
            const float4 b4 = s_b[j * 32 + lane];
            float4 o;
            o.x = (a0 * a_mul - a_sub) * w4.x + b4.x;
            o.y = (a1 * a_mul - a_sub) * w4.y + b4.y;
            o.z = (a2 * a_mul - a_sub) * w4.z + b4.z;
            o.w = (a3 * a_mul - a_sub) * w4.w + b4.w;
            orow[j * 32 + lane] = o;
        }

        if (!have_next) break;
        tok = ntok;
        scale = nscale;
    }
}

extern "C" void kernel_launch(void* const* d_in, const int* in_sizes, int n_in,
                              void* d_out, int out_size)
{
    const int*   x      = (const int*)d_in[0];
    const int*   w_i8   = (const int*)d_in[1];
    const float* absmax = (const float*)d_in[2];
    const float* code   = (const float*)d_in[3];
    const float* ln_w   = (const float*)d_in[4];
    const float* ln_b   = (const float*)d_in[5];
    float*       out    = (float*)d_out;

    const int n_tokens = in_sizes[0];   // 16384
    const int grid = 592;               // 4 CTAs x 148 SMs, one balanced wave

    frozen_bnb_emb_ln_kernel<<<grid, 256>>>(x, w_i8, absmax, code, ln_w, ln_b, out, n_tokens);
}

// round 15
// speedup vs baseline: 1.3653x; 1.3653x over previous
#include <cuda_runtime.h>
#include <cuda_bf16.h>

// FrozenBNBStableEmbedding: blockwise-int8 dequant embedding gather + LayerNorm.
//
// Inputs (metadata order):
//   0: x         int32  [8, 2048]    token ids (16384)
//   1: weight_i8 int32  [50304,1024] code indices 0..255
//   2: absmax    f32    [12576]      per-4096-elem block scale == per (row>>2)
//   3: code      f32    [256]        dequant codebook
//   4: ln_weight f32    [1024]
//   5: ln_bias   f32    [1024]
// Output: f32 [8, 2048, 1024]
//
// WARP-PER-TOKEN, PERSISTENT grid-stride pipeline (R11 layout + rolling prefetch):
//   - 8 int4 gathers/lane per token (MLP=8); next token's gather always in
//     flight while current token is reduced/normalized/stored
//   - single dequant pass, v[32] register-resident (no reg cap — 2 CTAs/SM)
//   - codebook replicated 32x in shared: bank == lane, conflict-free
//   - grid = 2 CTAs/SM x 148 SMs = one wave; only 1 cold gather per warp
//   - zero block barriers in the main loop (warp shfl reductions only)

#define D 1024
#define V 50304
#define EPS 1e-5f
#define WARPS_PER_CTA 8

__global__ __launch_bounds__(256)
void frozen_bnb_emb_ln_kernel(const int* __restrict__ x,
                              const int* __restrict__ weight_i8,
                              const float* __restrict__ absmax,
                              const float* __restrict__ code,
                              const float* __restrict__ ln_weight,
                              const float* __restrict__ ln_bias,
                              float* __restrict__ out,
                              int n_tokens)
{
    __shared__ float  s_rep[256 * 32];   // s_rep[idx*32 + lane] == code[idx]
    __shared__ float4 s_w[256];          // ln_weight as float4
    __shared__ float4 s_b[256];          // ln_bias  as float4

    const int tid  = threadIdx.x;
    const int warp = tid >> 5;
    const int lane = tid & 31;

    // ---- One-time staging (only barrier in the kernel) ----
    {
        const float cv = __ldg(&code[tid]);
        float* row = &s_rep[tid * 32];
        #pragma unroll
        for (int k = 0; k < 32; k++)
            row[(lane + k) & 31] = cv;           // distinct bank per lane
        s_w[tid] = __ldg(reinterpret_cast<const float4*>(ln_weight) + tid);
        s_b[tid] = __ldg(reinterpret_cast<const float4*>(ln_bias) + tid);
    }
    __syncthreads();

    const int stride = gridDim.x * WARPS_PER_CTA;    // total warps (persistent)
    int tok = blockIdx.x * WARPS_PER_CTA + warp;
    if (tok >= n_tokens) return;

    // ---- Cold prefetch of first token (only blocking gather this warp pays) ----
    int4  raw[8];
    float scale;
    {
        int r = min(max(__ldg(&x[tok]), 0), V - 1);
        scale = __ldg(&absmax[r >> 2]);
        const int4* wr = reinterpret_cast<const int4*>(weight_i8 + (long long)r * D);
        #pragma unroll
        for (int j = 0; j < 8; j++)
            raw[j] = __ldg(wr + j * 32 + lane);
    }

    while (true) {
        // ---- 1) Single dequant pass: raw codes -> v[32] (unscaled), stats ----
        float v[32];
        float s = 0.0f, sq = 0.0f;
        #pragma unroll
        for (int j = 0; j < 8; j++) {
            float a0 = s_rep[(raw[j].x & 255) * 32 + lane];
            float a1 = s_rep[(raw[j].y & 255) * 32 + lane];
            float a2 = s_rep[(raw[j].z & 255) * 32 + lane];
            float a3 = s_rep[(raw[j].w & 255) * 32 + lane];
            v[4*j+0] = a0; v[4*j+1] = a1; v[4*j+2] = a2; v[4*j+3] = a3;
            s  += a0 + a1 + a2 + a3;
            sq += a0*a0 + a1*a1 + a2*a2 + a3*a3;
        }

        // ---- 2) raw[] now dead: issue next token's gather (always in flight) ----
        const int  ntok = tok + stride;
        const bool have_next = (ntok < n_tokens);
        float nscale = 0.0f;
        if (have_next) {
            int rn = min(max(__ldg(&x[ntok]), 0), V - 1);
            nscale = __ldg(&absmax[rn >> 2]);
            const int4* wr = reinterpret_cast<const int4*>(weight_i8 + (long long)rn * D);
            #pragma unroll
            for (int j = 0; j < 8; j++)
                raw[j] = __ldg(wr + j * 32 + lane);
        }

        // ---- 3) Warp-only LayerNorm stats (scale folded in afterwards) ----
        #pragma unroll
        for (int off = 16; off > 0; off >>= 1) {
            s  += __shfl_xor_sync(0xFFFFFFFFu, s,  off);
            sq += __shfl_xor_sync(0xFFFFFFFFu, sq, off);
        }
        const float mean_u = s * (1.0f / D);                 // unscaled mean
        const float var    = (sq * (1.0f / D) - mean_u * mean_u) * scale * scale;
        const float rstd   = rsqrtf(var + EPS);
        const float a_mul  = scale * rstd;                   // v*scale normalized
        const float a_sub  = mean_u * scale * rstd;

        // ---- 4) Affine + coalesced float4 stores ----
        float4* orow = reinterpret_cast<float4*>(out + (long long)tok * D);
        #pragma unroll
        for (int j = 0; j < 8; j++) {
            const float4 w4 = s_w[j * 32 + lane];
            const float4 b4 = s_b[j * 32 + lane];
            float4 o;
            o.x = (v[4*j+0] * a_mul - a_sub) * w4.x + b4.x;
            o.y = (v[4*j+1] * a_mul - a_sub) * w4.y + b4.y;
            o.z = (v[4*j+2] * a_mul - a_sub) * w4.z + b4.z;
            o.w = (v[4*j+3] * a_mul - a_sub) * w4.w + b4.w;
            orow[j * 32 + lane] = o;
        }

        if (!have_next) break;
        tok   = ntok;
        scale = nscale;
    }
}

extern "C" void kernel_launch(void* const* d_in, const int* in_sizes, int n_in,
                              void* d_out, int out_size)
{
    const int*   x      = (const int*)d_in[0];
    const int*   w_i8   = (const int*)d_in[1];
    const float* absmax = (const float*)d_in[2];
    const float* code   = (const float*)d_in[3];
    const float* ln_w   = (const float*)d_in[4];
    const float* ln_b   = (const float*)d_in[5];
    float*       out    = (float*)d_out;

    const int n_tokens = in_sizes[0];   // 16384
    const int grid = 296;               // 2 CTAs/SM x 148 SMs: one persistent wave

    frozen_bnb_emb_ln_kernel<<<grid, 256>>>(x, w_i8, absmax, code, ln_w, ln_b, out, n_tokens);
}